// round 5
// baseline (speedup 1.0000x reference)
#include <cuda_runtime.h>

// LUT tree via packed f32x2: two rows per 64-bit lane value.
// Tables in shared, pre-differenced + duplicated [a,a,d,d] (one LDS.128 = both
// packed operands). Warp-level work stealing over 4-row tiles (atomic counter,
// reset kernel). 640 threads/CTA, 1 CTA/SM, next-tile prefetch under tail.

#define THREADS   640
#define NWARPS    20
#define GRID      152
#define N_ROWS    32768
#define NT        (N_ROWS / 4)       // 8192 tiles of 4 rows (2 pairs)

#define NODE_F    36                 // 32 floats [a,a,d,d]x8 + 4 pad (144B stride)
#define OFF0      0
#define OFF1      (256 * NODE_F)
#define OFF2      (OFF1 + 64 * NODE_F)
#define OFF3      (OFF2 + 16 * NODE_F)
#define OFF4      (OFF3 + 4 * NODE_F)
#define TTOT      (OFF4 + NODE_F)    // 12276 floats
#define TTOT_B    (TTOT * 4)         // 49104 B
#define PAIR_B    2560               // 256 nodes * 8B + 16B pad per 8 nodes
#define WXCH_B    (2 * PAIR_B)       // 5120 B per warp
#define SMEM_B    (TTOT_B + NWARPS * WXCH_B)   // 151504 B

typedef unsigned long long u64;

__device__ unsigned g_ctr;
__global__ void reset_ctr() { g_ctr = 0; }

__device__ __forceinline__ u64 fma2(u64 x, u64 b, u64 a) {
    u64 r; asm("fma.rn.f32x2 %0, %1, %2, %3;" : "=l"(r) : "l"(x), "l"(b), "l"(a));
    return r;
}
__device__ __forceinline__ u64 pack2(float lo, float hi) {
    u64 r; asm("mov.b64 %0, {%1, %2};" : "=l"(r) : "f"(lo), "f"(hi));
    return r;
}
__device__ __forceinline__ void unpack2(u64 v, float& lo, float& hi) {
    asm("mov.b64 {%0, %1}, %2;" : "=f"(lo), "=f"(hi) : "l"(v));
}
// lerp(a,b,x) = a + x*(b-a);  (b-a) = fma((-1,-1), a, b)  -> fma-only
__device__ __forceinline__ u64 lerp2(u64 a, u64 b, u64 x, u64 M1) {
    return fma2(x, fma2(M1, a, b), a);
}
__device__ __forceinline__ u64 db(double d) { return __double_as_longlong(d); }

// one packed node from a duplicated+prediffed table (8 x double2 = [a,a | d,d])
__device__ __forceinline__ u64 node2(const float* tp, u64 x0, u64 x1, u64 x2, u64 x3,
                                     u64 M1) {
    const double2* q = (const double2*)tp;
    u64 v[8];
    #pragma unroll
    for (int k = 0; k < 8; ++k) {
        double2 c = q[k];
        v[k] = fma2(x0, db(c.y), db(c.x));
    }
    u64 w0 = lerp2(v[0], v[1], x1, M1);
    u64 w1 = lerp2(v[2], v[3], x1, M1);
    u64 w2 = lerp2(v[4], v[5], x1, M1);
    u64 w3 = lerp2(v[6], v[7], x1, M1);
    u64 z0 = lerp2(w0, w1, x2, M1);
    u64 z1 = lerp2(w2, w3, x2, M1);
    return lerp2(z0, z1, x3, M1);
}

__device__ __forceinline__ void load_pack(const float4* xp, int idx, u64 X[2][4]) {
    float4 a0 = xp[idx], b0 = xp[256 + idx];
    float4 a1 = xp[512 + idx], b1 = xp[768 + idx];
    X[0][0] = pack2(a0.x, b0.x); X[0][1] = pack2(a0.y, b0.y);
    X[0][2] = pack2(a0.z, b0.z); X[0][3] = pack2(a0.w, b0.w);
    X[1][0] = pack2(a1.x, b1.x); X[1][1] = pack2(a1.y, b1.y);
    X[1][2] = pack2(a1.z, b1.z); X[1][3] = pack2(a1.w, b1.w);
}

__global__ void __launch_bounds__(THREADS, 1) lut_tree_kernel(
    const float* __restrict__ x,
    const float* __restrict__ t0, const float* __restrict__ t1,
    const float* __restrict__ t2, const float* __restrict__ t3,
    const float* __restrict__ t4,
    float* __restrict__ out)
{
    extern __shared__ __align__(16) char smem_raw[];
    float* sh_t = (float*)smem_raw;

    // ---- cooperative table load: pre-differenced + duplicated [a,a,d,d] ----
    {
        const float* tabs[5] = {t0, t1, t2, t3, t4};
        // global node id g: 0..255 -> L0, 256..319 -> L1, 320..335 -> L2,
        // 336..339 -> L3, 340 -> L4
        for (int i = threadIdx.x; i < 341 * 8; i += THREADS) {
            int g = i >> 3, k = i & 7;
            int L, ln, baseF;
            if (g < 256)      { L = 0; ln = g;       baseF = OFF0; }
            else if (g < 320) { L = 1; ln = g - 256; baseF = OFF1; }
            else if (g < 336) { L = 2; ln = g - 320; baseF = OFF2; }
            else if (g < 340) { L = 3; ln = g - 336; baseF = OFF3; }
            else              { L = 4; ln = 0;       baseF = OFF4; }
            float a = tabs[L][ln * 16 + 2 * k];
            float b = tabs[L][ln * 16 + 2 * k + 1];
            float* dst = sh_t + baseF + ln * NODE_F + 4 * k;
            dst[0] = a; dst[1] = a; dst[2] = b - a; dst[3] = b - a;
        }
    }
    __syncthreads();

    const int warp = threadIdx.x >> 5;
    const int lane = threadIdx.x & 31;
    const unsigned FULL = 0xffffffffu;
    const u64 M1 = pack2(-1.0f, -1.0f);

    char* xch = smem_raw + TTOT_B + warp * WXCH_B;

    unsigned t;
    if (lane == 0) t = atomicAdd(&g_ctr, 1);
    t = __shfl_sync(FULL, t, 0);

    u64 Xc[2][4];
    const float4* xp = (const float4*)x + (size_t)t * 1024;   // 4 rows * 256 f4
    if (t < NT) load_pack(xp, lane, Xc);

    while (t < NT) {
        // ---- layer 0: 8 node-groups, tables loaded once per j, 2 pairs ----
        #pragma unroll
        for (int j = 0; j < 8; ++j) {
            u64 Xn[2][4];
            if (j < 7) load_pack(xp, (j + 1) * 32 + lane, Xn);

            const double2* tq = (const double2*)(sh_t + (j * 32 + lane) * NODE_F);
            u64 v0[8], v1[8];
            #pragma unroll
            for (int k = 0; k < 8; ++k) {
                double2 c = tq[k];
                u64 qa = db(c.x), qd = db(c.y);
                v0[k] = fma2(Xc[0][0], qd, qa);
                v1[k] = fma2(Xc[1][0], qd, qa);
            }
            #pragma unroll
            for (int p = 0; p < 2; ++p) {
                u64* v = p ? v1 : v0;
                u64 xy = Xc[p][1], xz = Xc[p][2], xw = Xc[p][3];
                u64 w0 = lerp2(v[0], v[1], xy, M1);
                u64 w1 = lerp2(v[2], v[3], xy, M1);
                u64 w2 = lerp2(v[4], v[5], xy, M1);
                u64 w3 = lerp2(v[6], v[7], xy, M1);
                u64 z0 = lerp2(w0, w1, xz, M1);
                u64 z1 = lerp2(w2, w3, xz, M1);
                u64 res = lerp2(z0, z1, xw, M1);
                // node n=32j+lane as float2 at byte 8n + 16*(n>>3)
                *(u64*)(xch + p * PAIR_B + 320 * j + 8 * lane + 16 * (lane >> 3)) = res;
            }
            if (j < 7) {
                #pragma unroll
                for (int p = 0; p < 2; ++p)
                    #pragma unroll
                    for (int c = 0; c < 4; ++c) Xc[p][c] = Xn[p][c];
            }
        }

        // steal next tile + prefetch its first x batch under the tail compute
        unsigned t2;
        if (lane == 0) t2 = atomicAdd(&g_ctr, 1);
        t2 = __shfl_sync(FULL, t2, 0);
        const float4* xp2 = (const float4*)x + (size_t)t2 * 1024;
        if (t2 < NT) load_pack(xp2, lane, Xc);

        __syncwarp();

        // ---- layers 1..4 per pair ----
        #pragma unroll
        for (int p = 0; p < 2; ++p) {
            // lane l: L0 outputs 8l..8l+7 (conflict-free: 80B lane stride)
            const double2* ap = (const double2*)(xch + p * PAIR_B + 80 * lane);
            u64 A[8];
            #pragma unroll
            for (int i = 0; i < 4; ++i) {
                double2 m = ap[i];
                A[2 * i] = db(m.x); A[2 * i + 1] = db(m.y);
            }
            // layer 1: lane computes nodes 2l, 2l+1
            u64 z0 = node2(sh_t + OFF1 + (2 * lane) * NODE_F,
                           A[0], A[1], A[2], A[3], M1);
            u64 z1 = node2(sh_t + OFF1 + (2 * lane + 1) * NODE_F,
                           A[4], A[5], A[6], A[7], M1);
            // layer 2: node m = lane & 15
            int m = lane & 15;
            u64 b0 = __shfl_sync(FULL, z0, 2 * m);
            u64 b1 = __shfl_sync(FULL, z1, 2 * m);
            u64 b2 = __shfl_sync(FULL, z0, 2 * m + 1);
            u64 b3 = __shfl_sync(FULL, z1, 2 * m + 1);
            u64 w = node2(sh_t + OFF2 + m * NODE_F, b0, b1, b2, b3, M1);
            // layer 3: node q = lane & 3
            int qn = lane & 3;
            u64 c0 = __shfl_sync(FULL, w, 4 * qn + 0);
            u64 c1 = __shfl_sync(FULL, w, 4 * qn + 1);
            u64 c2 = __shfl_sync(FULL, w, 4 * qn + 2);
            u64 c3 = __shfl_sync(FULL, w, 4 * qn + 3);
            u64 vv = node2(sh_t + OFF3 + qn * NODE_F, c0, c1, c2, c3, M1);
            // layer 4
            u64 d0 = __shfl_sync(FULL, vv, 0);
            u64 d1 = __shfl_sync(FULL, vv, 1);
            u64 d2 = __shfl_sync(FULL, vv, 2);
            u64 d3 = __shfl_sync(FULL, vv, 3);
            if (lane == 0) {
                u64 f = node2(sh_t + OFF4, d0, d1, d2, d3, M1);
                float lo, hi; unpack2(f, lo, hi);
                *(float2*)(out + t * 4 + 2 * p) = make_float2(lo, hi);
            }
        }
        __syncwarp();

        t = t2;
        xp = xp2;
    }
}

extern "C" void kernel_launch(void* const* d_in, const int* in_sizes, int n_in,
                              void* d_out, int out_size) {
    const float* x  = (const float*)d_in[0];
    const float* t0 = (const float*)d_in[1];
    const float* t1 = (const float*)d_in[2];
    const float* t2 = (const float*)d_in[3];
    const float* t3 = (const float*)d_in[4];
    const float* t4 = (const float*)d_in[5];
    float* out = (float*)d_out;

    reset_ctr<<<1, 1>>>();
    cudaFuncSetAttribute(lut_tree_kernel,
                         cudaFuncAttributeMaxDynamicSharedMemorySize, SMEM_B);
    lut_tree_kernel<<<GRID, THREADS, SMEM_B>>>(x, t0, t1, t2, t3, t4, out);
}

// round 7
// speedup vs baseline: 1.3679x; 1.3679x over previous
#include <cuda_runtime.h>

// LUT tree, monomial-coefficient form.
// Loader Mobius-transforms each 16-entry corner table into multilinear monomial
// coefficients -> node eval is 15 pure FMAs, no FADD/MUL.
// Persistent warps steal 4-row tiles from a global counter; layer-0 x loads are
// double-prefetched through a DEPTH-4 register ring (8 batches % 4 == 0 -> ring
// phase is stable across tiles; the depth-3 ring in R6 was the correctness bug).
// Next tile is stolen at j==6 so its first 2 batches load under the tail layers.

#define THREADS  256
#define NWARPS   8
#define GRID     296            // 2 CTAs/SM * 148 SMs
#define G        4              // rows per tile

#define NODE_F   20             // 16 coefs + 4 pad -> 80B stride, conflict-free
#define N_NODES  341            // 256+64+16+4+1, by global node id g
#define TTOT     (N_NODES * NODE_F)
#define XCHF     (NWARPS * G * 256)
#define SMEM_B   ((TTOT + XCHF) * 4)   // 27280 + 32768 = 60048 B

typedef unsigned uns;
__device__ uns g_ctr;
__global__ void reset_ctr() { g_ctr = 0; }

// eval with monomial coefs c[16], index = b0 + 2b1 + 4b2 + 8b3 (bit i <-> x_i)
__device__ __forceinline__ float node_eval(const float* c, float4 xv) {
    float4 q0 = *(const float4*)(c + 0);
    float4 q1 = *(const float4*)(c + 4);
    float4 q2 = *(const float4*)(c + 8);
    float4 q3 = *(const float4*)(c + 12);
    float s0 = fmaf(xv.y, fmaf(xv.x, q0.w, q0.z), fmaf(xv.x, q0.y, q0.x));
    float s1 = fmaf(xv.y, fmaf(xv.x, q1.w, q1.z), fmaf(xv.x, q1.y, q1.x));
    float s2 = fmaf(xv.y, fmaf(xv.x, q2.w, q2.z), fmaf(xv.x, q2.y, q2.x));
    float s3 = fmaf(xv.y, fmaf(xv.x, q3.w, q3.z), fmaf(xv.x, q3.y, q3.x));
    return fmaf(xv.w, fmaf(xv.z, s3, s2), fmaf(xv.z, s1, s0));
}

__device__ __forceinline__ void load_batch(float4* B, const float4* xb, int j, int lane) {
    #pragma unroll
    for (int r = 0; r < G; ++r)
        B[r] = xb[r * 256 + j * 32 + lane];
}

__global__ void __launch_bounds__(THREADS, 2) lut_tree_kernel(
    const float* __restrict__ x,
    const float* __restrict__ t0, const float* __restrict__ t1,
    const float* __restrict__ t2, const float* __restrict__ t3,
    const float* __restrict__ t4,
    float* __restrict__ out, int nt)
{
    extern __shared__ __align__(16) float smem[];
    float* sh_t = smem;                 // [341][20] monomial coefs
    float* sh_x = smem + TTOT;          // [NWARPS][G][256] exchange

    // ---- loader: fetch 16 corners per node, Mobius transform, store padded ----
    for (int g = threadIdx.x; g < N_NODES; g += THREADS) {
        const float* src; int ln;
        if (g < 256)      { src = t0; ln = g; }
        else if (g < 320) { src = t1; ln = g - 256; }
        else if (g < 336) { src = t2; ln = g - 320; }
        else if (g < 340) { src = t3; ln = g - 336; }
        else              { src = t4; ln = 0; }
        float v[16];
        #pragma unroll
        for (int k = 0; k < 16; ++k) v[k] = src[ln * 16 + k];
        #pragma unroll
        for (int i = 0; i < 4; ++i)
            #pragma unroll
            for (int c = 0; c < 16; ++c)
                if (c & (1 << i)) v[c] -= v[c ^ (1 << i)];
        float* dst = sh_t + g * NODE_F;
        #pragma unroll
        for (int k = 0; k < 16; ++k) dst[k] = v[k];
    }
    __syncthreads();

    const int warp = threadIdx.x >> 5;
    const int lane = threadIdx.x & 31;
    const unsigned FULL = 0xffffffffu;
    float* xch = sh_x + warp * (G * 256);

    uns t;
    if (lane == 0) t = atomicAdd(&g_ctr, 1);
    t = __shfl_sync(FULL, t, 0);

    float4 B[4][G];                      // depth-4 ring: read B[j&3], write B[(j+2)&3]
    const float4* xb = (const float4*)x + (size_t)t * (G * 256);
    if (t < (uns)nt) {
        load_batch(B[0], xb, 0, lane);
        load_batch(B[1], xb, 1, lane);
    }

    while (t < (uns)nt) {
        uns tn = 0xffffffffu;
        const float4* xbn = xb;

        // ---- layer 0: prefetch depth 2, stream crosses into next tile ----
        #pragma unroll
        for (int j = 0; j < 8; ++j) {
            if (j < 6) {
                load_batch(B[(j + 2) & 3], xb, j + 2, lane);
            } else {
                if (j == 6) {
                    if (lane == 0) tn = atomicAdd(&g_ctr, 1);
                    tn = __shfl_sync(FULL, tn, 0);
                    xbn = (const float4*)x + (size_t)tn * (G * 256);
                }
                if (tn < (uns)nt)
                    load_batch(B[(j + 2) & 3], xbn, j - 6, lane);
            }
            const float* cp = sh_t + (j * 32 + lane) * NODE_F;
            float4 q0 = *(const float4*)(cp + 0);
            float4 q1 = *(const float4*)(cp + 4);
            float4 q2 = *(const float4*)(cp + 8);
            float4 q3 = *(const float4*)(cp + 12);
            #pragma unroll
            for (int r = 0; r < G; ++r) {
                float4 xv = B[j & 3][r];
                float s0 = fmaf(xv.y, fmaf(xv.x, q0.w, q0.z), fmaf(xv.x, q0.y, q0.x));
                float s1 = fmaf(xv.y, fmaf(xv.x, q1.w, q1.z), fmaf(xv.x, q1.y, q1.x));
                float s2 = fmaf(xv.y, fmaf(xv.x, q2.w, q2.z), fmaf(xv.x, q2.y, q2.x));
                float s3 = fmaf(xv.y, fmaf(xv.x, q3.w, q3.z), fmaf(xv.x, q3.y, q3.x));
                xch[r * 256 + j * 32 + lane] =
                    fmaf(xv.w, fmaf(xv.z, s3, s2), fmaf(xv.z, s1, s0));
            }
        }
        __syncwarp();

        // ---- layers 1..4 per row ----
        #pragma unroll
        for (int r = 0; r < G; ++r) {
            float4 a0 = *(const float4*)&xch[r * 256 + lane * 8];
            float4 a1 = *(const float4*)&xch[r * 256 + lane * 8 + 4];
            float z0 = node_eval(sh_t + (256 + 2 * lane) * NODE_F, a0);
            float z1 = node_eval(sh_t + (256 + 2 * lane + 1) * NODE_F, a1);

            float4 b;
            b.x = __shfl_sync(FULL, z0, (lane * 2) & 31);
            b.y = __shfl_sync(FULL, z1, (lane * 2) & 31);
            b.z = __shfl_sync(FULL, z0, (lane * 2 + 1) & 31);
            b.w = __shfl_sync(FULL, z1, (lane * 2 + 1) & 31);
            float w = node_eval(sh_t + (320 + (lane & 15)) * NODE_F, b);

            float4 c;
            c.x = __shfl_sync(FULL, w, (lane * 4 + 0) & 31);
            c.y = __shfl_sync(FULL, w, (lane * 4 + 1) & 31);
            c.z = __shfl_sync(FULL, w, (lane * 4 + 2) & 31);
            c.w = __shfl_sync(FULL, w, (lane * 4 + 3) & 31);
            float v = node_eval(sh_t + (336 + (lane & 3)) * NODE_F, c);

            float4 d;
            d.x = __shfl_sync(FULL, v, 0);
            d.y = __shfl_sync(FULL, v, 1);
            d.z = __shfl_sync(FULL, v, 2);
            d.w = __shfl_sync(FULL, v, 3);
            if (lane == 0)
                out[t * G + r] = node_eval(sh_t + 340 * NODE_F, d);
        }
        __syncwarp();

        t = tn;
        xb = xbn;
    }
}

extern "C" void kernel_launch(void* const* d_in, const int* in_sizes, int n_in,
                              void* d_out, int out_size) {
    const float* x  = (const float*)d_in[0];
    const float* t0 = (const float*)d_in[1];
    const float* t1 = (const float*)d_in[2];
    const float* t2 = (const float*)d_in[3];
    const float* t3 = (const float*)d_in[4];
    const float* t4 = (const float*)d_in[5];
    float* out = (float*)d_out;

    int n_rows = in_sizes[0] / 1024;       // 32768
    int nt = n_rows / G;                   // 8192 tiles

    reset_ctr<<<1, 1>>>();
    cudaFuncSetAttribute(lut_tree_kernel,
                         cudaFuncAttributeMaxDynamicSharedMemorySize, SMEM_B);
    lut_tree_kernel<<<GRID, THREADS, SMEM_B>>>(x, t0, t1, t2, t3, t4, out, nt);
}